// round 16
// baseline (speedup 1.0000x reference)
#include <cuda_runtime.h>

// Vanilla tanh RNN: B=512, S=4096, H=40, fp32.
// out = concat( [B*S] per-step fc outputs , [B*H] final hidden )
//
// R16 = R15 (barrier-free, branch-free, predicated stores) + split-LDS
// software pipelining. One warp per batch, one warp per CTA (512 x 32).
// h for step t lives in registers (hpA/hpB alternating). Each step:
//   fma block (40 packed fma.rn.f32x2, interleaved a/c accumulators)
//   a-tree -> tanh -> STS slots 0-31
//   LDS batch1 (pairs 0-15 of the just-written buffer) -> next hp   <- early!
//   c-tree -> tanh -> predicated STS slots 32-39
//   LDS batch2 (pairs 16-19) -> next hp
// The in-order LSU guarantees LDS-after-STS sees the data; all conditional
// stores are SASS @p predicated so the warp never diverges (no BSSY/BSYNC).
// tanh = single MUFU tanh.approx. Lane 8 stores fc z one step behind.

#define BATCH 512
#define SEQ   4096
#define HID   40
#define KCH   64
#define THREADS 32
#define FULLM 0xffffffffu

typedef unsigned long long u64;

__device__ __forceinline__ u64 pack2(float lo, float hi) {
    u64 r;
    asm("mov.b64 %0, {%1, %2};" : "=l"(r) : "f"(lo), "f"(hi));
    return r;
}
__device__ __forceinline__ void unpack2(u64 v, float& lo, float& hi) {
    asm("mov.b64 {%0, %1}, %2;" : "=f"(lo), "=f"(hi) : "l"(v));
}
__device__ __forceinline__ u64 fma2(u64 a, u64 b, u64 c) {
    u64 d;
    asm("fma.rn.f32x2 %0, %1, %2, %3;" : "=l"(d) : "l"(a), "l"(b), "l"(c));
    return d;
}
__device__ __forceinline__ void lds2(u64& a, u64& b, unsigned off) {
    asm volatile("ld.shared.v2.u64 {%0, %1}, [%2];"
                 : "=l"(a), "=l"(b) : "r"(off) : "memory");
}
__device__ __forceinline__ void sts1(unsigned off, float v) {
    asm volatile("st.shared.f32 [%0], %1;" :: "r"(off), "f"(v) : "memory");
}
// predicated shared store (no branch)
__device__ __forceinline__ void sts1_pred(unsigned off, float v, int pred) {
    asm volatile(
        "{\n\t"
        ".reg .pred p;\n\t"
        "setp.ne.s32 p, %2, 0;\n\t"
        "@p st.shared.f32 [%0], %1;\n\t"
        "}"
        :: "r"(off), "f"(v), "r"(pred) : "memory");
}
// predicated global store (no branch)
__device__ __forceinline__ void stg_pred(float* ptr, float v, int pred) {
    asm volatile(
        "{\n\t"
        ".reg .pred p;\n\t"
        "setp.ne.s32 p, %2, 0;\n\t"
        "@p st.global.f32 [%0], %1;\n\t"
        "}"
        :: "l"(ptr), "f"(v), "r"(pred) : "memory");
}
__device__ __forceinline__ float tanh_mufu(float z) {
    float r;
    asm("tanh.approx.f32 %0, %1;" : "=f"(r) : "f"(z));
    return r;
}

struct Lane {
    u64 wm[HID / 2], wx[HID / 2];
    float wih_m, cb_m, wih_x, cb_x;
};

// One step: consume hp (registers), write new h to shared buffer wr, and
// prefetch the next step's h from wr into hpn (split around the two stores).
__device__ __forceinline__ float rnn_step(
    const u64* __restrict__ hp, u64* __restrict__ hpn, unsigned wr,
    float ia, float ic, int l, int is_low8,
    const Lane& W, float& hm, float& hxv)
{
    u64 a0 = pack2(ia, 0.0f);
    u64 c0 = pack2(ic, 0.0f);
#pragma unroll
    for (int j = 0; j < HID / 2; j++) {
        a0 = fma2(W.wm[j], hp[j], a0);
        c0 = fma2(W.wx[j], hp[j], c0);
    }
    float alo, ahi;
    unpack2(a0, alo, ahi);
    hm = tanh_mufu(alo + ahi);
    sts1(wr + 4u * l, hm);                      // slots 0..31 written

    // batch1: next-step pairs 0..15 (bytes 0..127) — overlaps the c-tail
#pragma unroll
    for (int q = 0; q < 8; q++)
        lds2(hpn[2 * q], hpn[2 * q + 1], wr + 16u * q);

    float clo, chi;
    unpack2(c0, clo, chi);
    float zc = clo + chi;                       // lane>=8: fc.h + fc_b
    hxv = tanh_mufu(zc);
    sts1_pred(wr + 4u * (32 + l), hxv, is_low8); // slots 32..39 written

    // batch2: next-step pairs 16..19 (bytes 128..159)
    lds2(hpn[16], hpn[17], wr + 128u);
    lds2(hpn[18], hpn[19], wr + 144u);
    return zc;
}

__global__ void __launch_bounds__(THREADS, 8) rnn_kernel(
    const float* __restrict__ x,       // [B, S]
    const float* __restrict__ hidden,  // [B, H]
    const float* __restrict__ w_ih,    // [H]
    const float* __restrict__ w_hh,    // [H, H]
    const float* __restrict__ b_ih,    // [H]
    const float* __restrict__ b_hh,    // [H]
    const float* __restrict__ fc_w,    // [H]
    const float* __restrict__ fc_b,    // [1]
    float* __restrict__ out)           // [B*S] then [B*H]
{
    __shared__ __align__(16) float buf[2][HID];

    const int l  = threadIdx.x;        // one warp per CTA
    const int bg = blockIdx.x;
    const int is_low8 = (l < 8) ? 1 : 0;
    const int is_l8   = (l == 8) ? 1 : 0;

    Lane W;
#pragma unroll
    for (int j = 0; j < HID / 2; j++)
        W.wm[j] = pack2(w_hh[l * HID + 2 * j], w_hh[l * HID + 2 * j + 1]);

    const float* row2;
    if (l < 8) {
        row2 = &w_hh[(32 + l) * HID];
        W.wih_x = w_ih[32 + l];
        W.cb_x  = b_ih[32 + l] + b_hh[32 + l];
    } else {
        row2 = fc_w;
        W.wih_x = 0.0f;
        W.cb_x  = fc_b[0];
    }
#pragma unroll
    for (int j = 0; j < HID / 2; j++)
        W.wx[j] = pack2(row2[2 * j], row2[2 * j + 1]);

    W.wih_m = w_ih[l];
    W.cb_m  = b_ih[l] + b_hh[l];

    // initial state -> buf0, then preload hpA
    float hm = hidden[bg * HID + l];
    float hxv = 0.0f;
    buf[0][l] = hm;
    if (l < 8) {
        hxv = hidden[bg * HID + 32 + l];
        buf[0][32 + l] = hxv;
    }
    __syncthreads();

    const unsigned off0 = (unsigned)__cvta_generic_to_shared(&buf[0][0]);
    const unsigned off1 = (unsigned)__cvta_generic_to_shared(&buf[1][0]);

    u64 hpA[HID / 2], hpB[HID / 2];
#pragma unroll
    for (int q = 0; q < HID / 4; q++)
        lds2(hpA[2 * q], hpA[2 * q + 1], off0 + 16u * q);

    float xa = x[bg * SEQ + l];
    float xb = x[bg * SEQ + 32 + l];

    for (int chunk = 0; chunk < SEQ / KCH; chunk++) {
        const int t0  = chunk * KCH;
        const int t0n = (chunk + 1 < SEQ / KCH) ? t0 + KCH : 0;
        float xan = x[bg * SEQ + t0n + l];
        float xbn = x[bg * SEQ + t0n + 32 + l];

#pragma unroll 4
        for (int k = 0; k < KCH; k += 2) {
            // branchless per-pair prep: x broadcast + accumulator inits
            float xv0 = __shfl_sync(FULLM, (k & 32) ? xb : xa, k & 31);
            float xv1 = __shfl_sync(FULLM, ((k + 1) & 32) ? xb : xa, (k + 1) & 31);
            float ia0 = fmaf(xv0, W.wih_m, W.cb_m);
            float ic0 = fmaf(xv0, W.wih_x, W.cb_x);
            float ia1 = fmaf(xv1, W.wih_m, W.cb_m);
            float ic1 = fmaf(xv1, W.wih_x, W.cb_x);

            // even step: consume hpA, write buf1, prefetch hpB
            float zc0 = rnn_step(hpA, hpB, off1, ia0, ic0, l, is_low8, W, hm, hxv);
            {
                int ti = t0 + k;
                int tp = ti ? ti - 1 : 0;          // SEL, branchless
                stg_pred(out + bg * SEQ + tp, zc0, is_l8);
            }
            // odd step: consume hpB, write buf0, prefetch hpA
            float zc1 = rnn_step(hpB, hpA, off0, ia1, ic1, l, is_low8, W, hm, hxv);
            stg_pred(out + bg * SEQ + t0 + k, zc1, is_l8);
        }

        xa = xan;
        xb = xbn;
    }

    // ---- epilogue: out[S-1] = fc . h_{S-1} + fc_b ----
    // final h is in hpA (loaded from buf0 at the end of the last odd step)
    {
        u64 c0 = pack2(W.cb_x, 0.0f);
#pragma unroll
        for (int j = 0; j < HID / 2; j++)
            c0 = fma2(W.wx[j], hpA[j], c0);
        float clo, chi;
        unpack2(c0, clo, chi);
        stg_pred(out + bg * SEQ + SEQ - 1, clo + chi, is_l8);
    }

    // ---- final hidden ----
    out[BATCH * SEQ + bg * HID + l] = hm;
    if (l < 8) out[BATCH * SEQ + bg * HID + 32 + l] = hxv;
}

extern "C" void kernel_launch(void* const* d_in, const int* in_sizes, int n_in,
                              void* d_out, int out_size) {
    const float* x      = (const float*)d_in[0];
    const float* hidden = (const float*)d_in[1];
    const float* w_ih   = (const float*)d_in[2];
    const float* w_hh   = (const float*)d_in[3];
    const float* b_ih   = (const float*)d_in[4];
    const float* b_hh   = (const float*)d_in[5];
    const float* fc_w   = (const float*)d_in[6];
    const float* fc_b   = (const float*)d_in[7];
    float* out = (float*)d_out;

    rnn_kernel<<<BATCH, THREADS>>>(x, hidden, w_ih, w_hh, b_ih, b_hh,
                                   fc_w, fc_b, out);
}